// round 4
// baseline (speedup 1.0000x reference)
#include <cuda_runtime.h>
#include <math.h>

#define DIMM   1024
#define NHEADS 16
#define HDIM   64
#define BATCH  2
#define SEQ    2048
#define MROWS  (BATCH*SEQ)   // 4096
#define QKSCALE 0.125f       // 1/sqrt(64)

// ---------------- scratch (no allocs allowed) ----------------
__device__ float g_q[BATCH*NHEADS*SEQ*HDIM];   // [b][h][s][d]
__device__ float g_k[BATCH*NHEADS*SEQ*HDIM];
__device__ float g_v[BATCH*NHEADS*SEQ*HDIM];
__device__ float g_ctx[MROWS*DIMM];            // [b*s][h*64+d]

// ---------------------------------------------------------------------------
// Generic fp32 GEMM: C[M,N] = A[M,K] @ B[N,K]^T + bias[N]
// BM=BN=128, BK=8, 256 threads, 8x8 per-thread microtile.
// MODE 0: C row-major. MODE 1: scatter into g_q/g_k/g_v. MODE 2: A := g_ctx, C row-major.
// ---------------------------------------------------------------------------
template<int MODE>
__global__ __launch_bounds__(256, 2)
void sgemm_abT(const float* __restrict__ A, const float* __restrict__ Bm,
               const float* __restrict__ bias, float* __restrict__ C,
               int M, int N, int K)
{
    __shared__ float As[8][132];
    __shared__ float Bs[8][132];

    const float* Aptr = (MODE == 2) ? (const float*)g_ctx : A;

    int tid = threadIdx.x;
    int tx  = tid & 15;
    int ty  = tid >> 4;
    int bm  = blockIdx.y * 128;
    int bn  = blockIdx.x * 128;

    int lrow = tid >> 1;          // 0..127
    int lk   = (tid & 1) * 4;     // 0 or 4

    const float* Ag = Aptr + (size_t)(bm + lrow) * K + lk;
    const float* Bg = Bm   + (size_t)(bn + lrow) * K + lk;

    float acc[8][8];
#pragma unroll
    for (int i = 0; i < 8; i++)
#pragma unroll
        for (int j = 0; j < 8; j++) acc[i][j] = 0.f;

    for (int kt = 0; kt < K; kt += 8) {
        float4 av = *(const float4*)(Ag + kt);
        float4 bv = *(const float4*)(Bg + kt);
        __syncthreads();
        As[lk+0][lrow] = av.x; As[lk+1][lrow] = av.y;
        As[lk+2][lrow] = av.z; As[lk+3][lrow] = av.w;
        Bs[lk+0][lrow] = bv.x; Bs[lk+1][lrow] = bv.y;
        Bs[lk+2][lrow] = bv.z; Bs[lk+3][lrow] = bv.w;
        __syncthreads();
#pragma unroll
        for (int kk = 0; kk < 8; kk++) {
            float4 a0 = *(const float4*)&As[kk][ty*8];
            float4 a1 = *(const float4*)&As[kk][ty*8+4];
            float4 b0 = *(const float4*)&Bs[kk][tx*8];
            float4 b1 = *(const float4*)&Bs[kk][tx*8+4];
            float ar[8] = {a0.x,a0.y,a0.z,a0.w,a1.x,a1.y,a1.z,a1.w};
            float br[8] = {b0.x,b0.y,b0.z,b0.w,b1.x,b1.y,b1.z,b1.w};
#pragma unroll
            for (int i = 0; i < 8; i++)
#pragma unroll
                for (int j = 0; j < 8; j++)
                    acc[i][j] = fmaf(ar[i], br[j], acc[i][j]);
        }
    }

#pragma unroll
    for (int i = 0; i < 8; i++) {
        int m = bm + ty*8 + i;
#pragma unroll
        for (int j = 0; j < 8; j++) {
            int n = bn + tx*8 + j;
            float v = acc[i][j] + bias[n];
            if (MODE == 0 || MODE == 2) {
                C[(size_t)m * N + n] = v;
            } else {
                int t = n >> 10;          // which of q/k/v
                int r = n & 1023;
                int h = r >> 6;
                int d = r & 63;
                int b = m >> 11;
                int s = m & 2047;
                float* dst = (t == 0) ? g_q : (t == 1) ? g_k : g_v;
                dst[(((size_t)(b*NHEADS + h))*SEQ + s)*HDIM + d] = v;
            }
        }
    }
}

// ---------------------------------------------------------------------------
// Flash attention (fp32): one block = 64 queries of one (b,h).
// Streams 64-wide K/V tiles with online softmax. 256 threads, 4x4 microtiles.
// smem (dynamic): Qs[64][68] (d-major), Ks[64][68] (d-major), Ps[64][68] (k-major), Vs[64][64]
// ---------------------------------------------------------------------------
__global__ __launch_bounds__(256, 3)
void attn_kernel()
{
    extern __shared__ float sm[];
    float (*Qs)[68] = (float(*)[68])(sm);
    float (*Ks)[68] = (float(*)[68])(sm + 64*68);
    float (*Ps)[68] = (float(*)[68])(sm + 2*64*68);
    float (*Vs)[64] = (float(*)[64])(sm + 3*64*68);

    int tid = threadIdx.x;
    int tx  = tid & 15;
    int ty  = tid >> 4;
    int bh  = blockIdx.y;                 // b*16 + h
    int q0  = blockIdx.x * 64;

    const float* Qg = g_q + (size_t)bh * SEQ * HDIM;
    const float* Kg = g_k + (size_t)bh * SEQ * HDIM;
    const float* Vg = g_v + (size_t)bh * SEQ * HDIM;

    // Load Q tile transposed ([d][r]), pre-scaled by 1/sqrt(Dh).
    for (int idx = tid; idx < 64*16; idx += 256) {
        int r  = idx & 63;
        int d4 = (idx >> 6) * 4;
        float4 v = *(const float4*)(Qg + (size_t)(q0 + r) * HDIM + d4);
        Qs[d4+0][r] = v.x * QKSCALE;
        Qs[d4+1][r] = v.y * QKSCALE;
        Qs[d4+2][r] = v.z * QKSCALE;
        Qs[d4+3][r] = v.w * QKSCALE;
    }

    float mrow[4], lrow[4], o[4][4];
#pragma unroll
    for (int i = 0; i < 4; i++) {
        mrow[i] = -INFINITY; lrow[i] = 0.f;
#pragma unroll
        for (int j = 0; j < 4; j++) o[i][j] = 0.f;
    }

    for (int kt = 0; kt < SEQ; kt += 64) {
        __syncthreads();   // prev-iter consumers of Ks/Vs/Ps done; Qs ready (1st iter)
        // K tile transposed ([d][c])
        for (int idx = tid; idx < 64*16; idx += 256) {
            int c  = idx & 63;
            int d4 = (idx >> 6) * 4;
            float4 v = *(const float4*)(Kg + (size_t)(kt + c) * HDIM + d4);
            Ks[d4+0][c] = v.x; Ks[d4+1][c] = v.y;
            Ks[d4+2][c] = v.z; Ks[d4+3][c] = v.w;
        }
        // V tile natural ([k][d])
        for (int idx = tid; idx < 64*16; idx += 256) {
            int r  = idx >> 4;
            int d4 = (idx & 15) * 4;
            *(float4*)&Vs[r][d4] = *(const float4*)(Vg + (size_t)(kt + r) * HDIM + d4);
        }
        __syncthreads();

        // S = (Q*scale) @ K^T  -> s[4][4]
        float s[4][4];
#pragma unroll
        for (int i = 0; i < 4; i++)
#pragma unroll
            for (int j = 0; j < 4; j++) s[i][j] = 0.f;
#pragma unroll 16
        for (int kk = 0; kk < HDIM; kk++) {
            float4 qv = *(const float4*)&Qs[kk][ty*4];
            float4 kv = *(const float4*)&Ks[kk][tx*4];
            float qr[4] = {qv.x,qv.y,qv.z,qv.w};
            float kr[4] = {kv.x,kv.y,kv.z,kv.w};
#pragma unroll
            for (int i = 0; i < 4; i++)
#pragma unroll
                for (int j = 0; j < 4; j++)
                    s[i][j] = fmaf(qr[i], kr[j], s[i][j]);
        }

        // online softmax (rows split across 16 tx lanes; lane-aligned 16-groups)
#pragma unroll
        for (int i = 0; i < 4; i++) {
            float rmax = fmaxf(fmaxf(s[i][0], s[i][1]), fmaxf(s[i][2], s[i][3]));
#pragma unroll
            for (int ofs = 8; ofs > 0; ofs >>= 1)
                rmax = fmaxf(rmax, __shfl_xor_sync(0xffffffffu, rmax, ofs));
            float mnew  = fmaxf(mrow[i], rmax);
            float alpha = __expf(mrow[i] - mnew);
            float rsum = 0.f;
#pragma unroll
            for (int j = 0; j < 4; j++) {
                s[i][j] = __expf(s[i][j] - mnew);
                rsum += s[i][j];
            }
#pragma unroll
            for (int ofs = 8; ofs > 0; ofs >>= 1)
                rsum += __shfl_xor_sync(0xffffffffu, rsum, ofs);
            lrow[i] = lrow[i] * alpha + rsum;
#pragma unroll
            for (int j = 0; j < 4; j++) o[i][j] *= alpha;
            mrow[i] = mnew;
        }

        // stage P transposed ([k][r])
#pragma unroll
        for (int i = 0; i < 4; i++)
#pragma unroll
            for (int j = 0; j < 4; j++)
                Ps[tx*4+j][ty*4+i] = s[i][j];
        __syncthreads();

        // O += P @ V
#pragma unroll 16
        for (int kk = 0; kk < 64; kk++) {
            float4 pv = *(const float4*)&Ps[kk][ty*4];
            float4 vv = *(const float4*)&Vs[kk][tx*4];
            float pr[4] = {pv.x,pv.y,pv.z,pv.w};
            float vr[4] = {vv.x,vv.y,vv.z,vv.w};
#pragma unroll
            for (int i = 0; i < 4; i++)
#pragma unroll
                for (int j = 0; j < 4; j++)
                    o[i][j] = fmaf(pr[i], vr[j], o[i][j]);
        }
    }

    // epilogue: normalize + write ctx [b][s][h*64+d]
    int b = bh >> 4;
    int h = bh & 15;
#pragma unroll
    for (int i = 0; i < 4; i++) {
        float inv = 1.f / lrow[i];
        int srow = q0 + ty*4 + i;
        size_t base = ((size_t)(b*SEQ + srow))*DIMM + h*HDIM + tx*4;
#pragma unroll
        for (int j = 0; j < 4; j++)
            g_ctx[base + j] = o[i][j] * inv;
    }
}

// ---------------------------------------------------------------------------
extern "C" void kernel_launch(void* const* d_in, const int* in_sizes, int n_in,
                              void* d_out, int out_size)
{
    const float* x      = (const float*)d_in[0];
    const float* qkv_w  = (const float*)d_in[1];
    const float* qkv_b  = (const float*)d_in[2];
    const float* proj_w = (const float*)d_in[3];
    const float* proj_b = (const float*)d_in[4];
    float* out = (float*)d_out;

    (void)in_sizes; (void)n_in; (void)out_size;

    static const int ATTN_SMEM = (3*64*68 + 64*64) * (int)sizeof(float);  // 68608 B
    cudaFuncSetAttribute(attn_kernel, cudaFuncAttributeMaxDynamicSharedMemorySize, ATTN_SMEM);

    dim3 blk(256);
    // 1) QKV projection, scattered into q/k/v scratch
    sgemm_abT<1><<<dim3(3*DIMM/128, MROWS/128), blk>>>(x, qkv_w, qkv_b, nullptr,
                                                       MROWS, 3*DIMM, DIMM);
    // 2) attention
    attn_kernel<<<dim3(SEQ/64, BATCH*NHEADS), blk, ATTN_SMEM>>>();
    // 3) output projection
    sgemm_abT<2><<<dim3(DIMM/128, MROWS/128), blk>>>(nullptr, proj_w, proj_b, out,
                                                     MROWS, DIMM, DIMM);
}

// round 8
// speedup vs baseline: 2.6124x; 2.6124x over previous
#include <cuda_runtime.h>
#include <cstdint>
#include <math.h>

#define SEQ 2048
#define MR  4096

// ---------------- scratch (device globals; no allocs) ----------------
__device__ float g_xr [MR*1024];            // x rounded to tf32
__device__ float g_wr [3*1024*1024];        // qkv_w rounded
__device__ float g_pwr[1024*1024];          // proj_w rounded
__device__ float g_qkv[(size_t)MR*3072];    // q(*0.125)|k|v rounded, row-major [s][3072]
__device__ float g_ctx[(size_t)MR*1024];    // attention out rounded

// ---------------- helpers ----------------
__device__ __forceinline__ uint32_t sm_u32(const void* p){
    uint32_t a;
    asm("{ .reg .u64 t; cvta.to.shared.u64 t, %1; cvt.u32.u64 %0, t; }" : "=r"(a) : "l"(p));
    return a;
}
__device__ __forceinline__ float rnaf(float x){
    uint32_t u; asm("cvt.rna.tf32.f32 %0, %1;" : "=r"(u) : "f"(x)); return __uint_as_float(u);
}
#define CP16(dst,src) asm volatile("cp.async.cg.shared.global [%0], [%1], 16;" :: "r"(dst),"l"(src))
#define CPC()  asm volatile("cp.async.commit_group;")
#define CPW(n) asm volatile("cp.async.wait_group %0;" :: "n"(n))

__device__ __forceinline__ void mma8(float* c, const uint32_t* a, const uint32_t* b){
    asm volatile("mma.sync.aligned.m16n8k8.row.col.f32.tf32.tf32.f32 "
        "{%0,%1,%2,%3}, {%4,%5,%6,%7}, {%8,%9}, {%0,%1,%2,%3};"
        : "+f"(c[0]),"+f"(c[1]),"+f"(c[2]),"+f"(c[3])
        : "r"(a[0]),"r"(a[1]),"r"(a[2]),"r"(a[3]), "r"(b[0]),"r"(b[1]));
}

// ---------------------------------------------------------------------------
// fp32 -> tf32 (rna) pre-round. which: 0->g_xr, 1->g_wr, 2->g_pwr
// ---------------------------------------------------------------------------
__global__ void round_k(const float4* __restrict__ in, int which, int n4)
{
    int i = blockIdx.x * blockDim.x + threadIdx.x;
    if (i >= n4) return;
    float4* out = (which==0) ? (float4*)g_xr : (which==1) ? (float4*)g_wr : (float4*)g_pwr;
    float4 v = in[i];
    v.x = rnaf(v.x); v.y = rnaf(v.y); v.z = rnaf(v.z); v.w = rnaf(v.w);
    out[i] = v;
}

// ---------------------------------------------------------------------------
// tf32 mma.sync GEMM: C[M,N] = A[M,1024] @ B[N,1024]^T + bias
// 128x128 tile, BK=16, 2-stage cp.async, 256 thr, warp tile 32x64.
// MODE 1: A=g_xr, B=g_wr, N=3072 -> g_qkv (rounded; q cols scaled 0.125)
// MODE 2: A=g_ctx, B=g_pwr, N=1024 -> C (plain fp32)
// ---------------------------------------------------------------------------
template<int MODE>
__global__ __launch_bounds__(256)
void mm_mma(const float* __restrict__ bias, float* __restrict__ C)
{
    const int K = 1024;
    const int N = (MODE==1) ? 3072 : 1024;
    __shared__ float As[2][128][20];
    __shared__ float Bs[2][128][20];
    const float* Ap = (MODE==1) ? g_xr : g_ctx;
    const float* Bp = (MODE==1) ? g_wr : g_pwr;
    float* Cp = (MODE==1) ? g_qkv : C;

    int tid = threadIdx.x, wid = tid>>5, lane = tid&31;
    int g = lane>>2, tg = lane&3;
    int wm = wid&3, wn = wid>>2;
    int bm = blockIdx.y*128, bn = blockIdx.x*128;

    uint32_t asb = sm_u32(As), bsb = sm_u32(Bs);

    auto pf = [&](int kt, int st){
        int r  = tid >> 1;
        int g4 = (tid & 1) * 2;
        uint32_t ao = asb + (uint32_t)((st*128 + r)*20)*4;
        uint32_t bo = bsb + (uint32_t)((st*128 + r)*20)*4;
        const float* aS = Ap + (size_t)(bm + r)*K + kt*16;
        const float* bS = Bp + (size_t)(bn + r)*K + kt*16;
        CP16(ao + (uint32_t)g4*16,     aS + g4*4);
        CP16(ao + (uint32_t)(g4+1)*16, aS + (g4+1)*4);
        CP16(bo + (uint32_t)g4*16,     bS + g4*4);
        CP16(bo + (uint32_t)(g4+1)*16, bS + (g4+1)*4);
    };

    float acc[2][8][4];
#pragma unroll
    for (int mt=0; mt<2; mt++)
#pragma unroll
        for (int nt=0; nt<8; nt++)
#pragma unroll
            for (int q=0; q<4; q++) acc[mt][nt][q] = 0.f;

    pf(0, 0); CPC();
    for (int kt = 0; kt < 64; kt++){
        int st = kt & 1;
        if (kt + 1 < 64) { pf(kt+1, st^1); CPC(); CPW(1); } else CPW(0);
        __syncthreads();
#pragma unroll
        for (int k8 = 0; k8 < 2; k8++){
            uint32_t a[2][4], b[8][2];
#pragma unroll
            for (int mt=0; mt<2; mt++){
                const float* p = &As[st][wm*32 + mt*16 + g][k8*8 + tg];
                a[mt][0] = __float_as_uint(p[0]);
                a[mt][1] = __float_as_uint(p[8*20]);
                a[mt][2] = __float_as_uint(p[4]);
                a[mt][3] = __float_as_uint(p[8*20 + 4]);
            }
#pragma unroll
            for (int nt=0; nt<8; nt++){
                const float* p = &Bs[st][wn*64 + nt*8 + g][k8*8 + tg];
                b[nt][0] = __float_as_uint(p[0]);
                b[nt][1] = __float_as_uint(p[4]);
            }
#pragma unroll
            for (int mt=0; mt<2; mt++)
#pragma unroll
                for (int nt=0; nt<8; nt++)
                    mma8(acc[mt][nt], a[mt], b[nt]);
        }
        __syncthreads();
    }

#pragma unroll
    for (int mt=0; mt<2; mt++){
        int r0 = bm + wm*32 + mt*16 + g;
#pragma unroll
        for (int nt=0; nt<8; nt++){
            int c0 = bn + wn*64 + nt*8 + 2*tg;
            float b0 = bias[c0], b1 = bias[c0+1];
            float v0 = acc[mt][nt][0] + b0, v1 = acc[mt][nt][1] + b1;
            float v2 = acc[mt][nt][2] + b0, v3 = acc[mt][nt][3] + b1;
            if (MODE == 1){
                float sc = (c0 < 1024) ? 0.125f : 1.f;   // fold qk scale into q
                v0 = rnaf(v0*sc); v1 = rnaf(v1*sc);
                v2 = rnaf(v2*sc); v3 = rnaf(v3*sc);
            }
            *(float2*)&Cp[(size_t)r0*N + c0]     = make_float2(v0, v1);
            *(float2*)&Cp[(size_t)(r0+8)*N + c0] = make_float2(v2, v3);
        }
    }
}

// ---------------------------------------------------------------------------
// Flash attention via mma.sync tf32. CTA = 128 queries of one (b,h), 256 thr,
// 8 warps x 16 rows. Bc=64 keys/iter, 32 iters. Online softmax in registers.
// dyn smem: Qs[128][76] | Ks[2][64][76] | Vs[2][64][76] | Ps[128][76]
// ---------------------------------------------------------------------------
__global__ __launch_bounds__(256)
void attn_mma()
{
    extern __shared__ float sm[];
    float (*Qs)[76] = (float(*)[76])(sm);
    float (*Ks)[64][76] = (float(*)[64][76])(sm + 128*76);
    float (*Vs)[64][76] = (float(*)[64][76])(sm + 128*76 + 2*64*76);
    float (*Ps)[76] = (float(*)[76])(sm + 128*76 + 4*64*76);

    int tid = threadIdx.x, wid = tid>>5, lane = tid&31;
    int g = lane>>2, tg = lane&3;
    int bh = blockIdx.y, b = bh>>4, h = bh&15;
    int q0 = blockIdx.x * 128;

    const float* Qg = g_qkv + (size_t)(b*2048 + q0)*3072 + h*64;
    const float* KVg = g_qkv + (size_t)(b*2048)*3072 + 1024 + h*64;

    uint32_t ksb = sm_u32(Ks), vsb = sm_u32(Vs);

    // Q tile (already *0.125, tf32-rounded)
    for (int i = tid; i < 128*16; i += 256){
        int r = i >> 4, c4 = i & 15;
        *(float4*)&Qs[r][c4*4] = *(const float4*)(Qg + (size_t)r*3072 + c4*4);
    }

    auto pf = [&](int it, int st){
        int kt = it * 64;
#pragma unroll
        for (int t = 0; t < 4; t++){
            int idx = t*256 + tid;
            int r = idx >> 4, c4 = idx & 15;
            uint32_t off = (uint32_t)((st*64 + r)*76 + c4*4)*4;
            const float* src = KVg + (size_t)(kt + r)*3072 + c4*4;
            CP16(ksb + off, src);           // K
            CP16(vsb + off, src + 1024);    // V
        }
    };

    float o[8][4], l0 = 0.f, l1 = 0.f, m0 = -1e30f, m1 = -1e30f;
#pragma unroll
    for (int nt=0; nt<8; nt++)
#pragma unroll
        for (int q=0; q<4; q++) o[nt][q] = 0.f;

    pf(0, 0); CPC();
    for (int it = 0; it < 32; it++){
        int st = it & 1;
        if (it + 1 < 32) { pf(it+1, st^1); CPC(); CPW(1); } else CPW(0);
        __syncthreads();

        // ---- S = Q @ K^T  (warp rows wid*16..wid*16+15) ----
        float s[8][4];
#pragma unroll
        for (int nt=0; nt<8; nt++)
#pragma unroll
            for (int q=0; q<4; q++) s[nt][q] = 0.f;
#pragma unroll
        for (int k8 = 0; k8 < 8; k8++){
            uint32_t a[4], bf[8][2];
            const float* p = &Qs[wid*16 + g][k8*8 + tg];
            a[0] = __float_as_uint(p[0]);
            a[1] = __float_as_uint(p[8*76]);
            a[2] = __float_as_uint(p[4]);
            a[3] = __float_as_uint(p[8*76 + 4]);
#pragma unroll
            for (int nt=0; nt<8; nt++){
                const float* q_ = &Ks[st][nt*8 + g][k8*8 + tg];
                bf[nt][0] = __float_as_uint(q_[0]);
                bf[nt][1] = __float_as_uint(q_[4]);
            }
#pragma unroll
            for (int nt=0; nt<8; nt++) mma8(s[nt], a, bf[nt]);
        }

        // ---- online softmax (rows r0 = wid*16+g, r1 = r0+8) ----
        float mx0 = -1e30f, mx1 = -1e30f;
#pragma unroll
        for (int nt=0; nt<8; nt++){
            mx0 = fmaxf(mx0, fmaxf(s[nt][0], s[nt][1]));
            mx1 = fmaxf(mx1, fmaxf(s[nt][2], s[nt][3]));
        }
        mx0 = fmaxf(mx0, __shfl_xor_sync(0xffffffffu, mx0, 1));
        mx0 = fmaxf(mx0, __shfl_xor_sync(0xffffffffu, mx0, 2));
        mx1 = fmaxf(mx1, __shfl_xor_sync(0xffffffffu, mx1, 1));
        mx1 = fmaxf(mx1, __shfl_xor_sync(0xffffffffu, mx1, 2));
        float mn0 = fmaxf(m0, mx0), mn1 = fmaxf(m1, mx1);
        float al0 = __expf(m0 - mn0), al1 = __expf(m1 - mn1);
        m0 = mn0; m1 = mn1;
        float sum0 = 0.f, sum1 = 0.f;
#pragma unroll
        for (int nt=0; nt<8; nt++){
            s[nt][0] = __expf(s[nt][0] - mn0); sum0 += s[nt][0];
            s[nt][1] = __expf(s[nt][1] - mn0); sum0 += s[nt][1];
            s[nt][2] = __expf(s[nt][2] - mn1); sum1 += s[nt][2];
            s[nt][3] = __expf(s[nt][3] - mn1); sum1 += s[nt][3];
        }
        sum0 += __shfl_xor_sync(0xffffffffu, sum0, 1);
        sum0 += __shfl_xor_sync(0xffffffffu, sum0, 2);
        sum1 += __shfl_xor_sync(0xffffffffu, sum1, 1);
        sum1 += __shfl_xor_sync(0xffffffffu, sum1, 2);
        l0 = l0*al0 + sum0; l1 = l1*al1 + sum1;
#pragma unroll
        for (int nt=0; nt<8; nt++){
            o[nt][0] *= al0; o[nt][1] *= al0;
            o[nt][2] *= al1; o[nt][3] *= al1;
        }
        // stage P (tf32-rounded) — own-warp rows only
        int pr = wid*16 + g;
#pragma unroll
        for (int nt=0; nt<8; nt++){
            *(float2*)&Ps[pr][nt*8 + 2*tg]   = make_float2(rnaf(s[nt][0]), rnaf(s[nt][1]));
            *(float2*)&Ps[pr+8][nt*8 + 2*tg] = make_float2(rnaf(s[nt][2]), rnaf(s[nt][3]));
        }
        __syncwarp();

        // ---- O += P @ V ----
#pragma unroll
        for (int k8 = 0; k8 < 8; k8++){
            uint32_t a[4], bf[8][2];
            const float* p = &Ps[wid*16 + g][k8*8 + tg];
            a[0] = __float_as_uint(p[0]);
            a[1] = __float_as_uint(p[8*76]);
            a[2] = __float_as_uint(p[4]);
            a[3] = __float_as_uint(p[8*76 + 4]);
#pragma unroll
            for (int nt=0; nt<8; nt++){
                const float* q_ = &Vs[st][k8*8 + tg][nt*8 + g];
                bf[nt][0] = __float_as_uint(q_[0]);
                bf[nt][1] = __float_as_uint(q_[4*76]);
            }
#pragma unroll
            for (int nt=0; nt<8; nt++) mma8(o[nt], a, bf[nt]);
        }
        __syncthreads();
    }

    // epilogue: normalize, round, write ctx
    float i0 = 1.f / l0, i1 = 1.f / l1;
    int r0 = q0 + wid*16 + g;
    float* Cg = g_ctx + (size_t)(b*2048 + r0)*1024 + h*64;
#pragma unroll
    for (int nt=0; nt<8; nt++){
        int c = nt*8 + 2*tg;
        *(float2*)&Cg[c] = make_float2(rnaf(o[nt][0]*i0), rnaf(o[nt][1]*i0));
        *(float2*)&Cg[8*1024 + c] = make_float2(rnaf(o[nt][2]*i1), rnaf(o[nt][3]*i1));
    }
}

// ---------------------------------------------------------------------------
extern "C" void kernel_launch(void* const* d_in, const int* in_sizes, int n_in,
                              void* d_out, int out_size)
{
    const float* x      = (const float*)d_in[0];
    const float* qkv_w  = (const float*)d_in[1];
    const float* qkv_b  = (const float*)d_in[2];
    const float* proj_w = (const float*)d_in[3];
    const float* proj_b = (const float*)d_in[4];
    float* out = (float*)d_out;
    (void)in_sizes; (void)n_in; (void)out_size;

    const int ASM = (128*76 + 4*64*76 + 128*76) * 4;   // 155648 B
    cudaFuncSetAttribute(attn_mma, cudaFuncAttributeMaxDynamicSharedMemorySize, ASM);

    round_k<<<4096, 256>>>((const float4*)x,      0, 1048576);
    round_k<<<3072, 256>>>((const float4*)qkv_w,  1,  786432);
    round_k<<<1024, 256>>>((const float4*)proj_w, 2,  262144);

    mm_mma<1><<<dim3(24, 32), 256>>>(qkv_b, nullptr);
    attn_mma  <<<dim3(16, 32), 256, ASM>>>();
    mm_mma<2><<<dim3( 8, 32), 256>>>(proj_b, out);
}

// round 10
// speedup vs baseline: 3.8456x; 1.4721x over previous
#include <cuda_runtime.h>
#include <cstdint>
#include <math.h>

#define SEQ 2048
#define MR  4096

// ---------------- scratch (device globals; no allocs) ----------------
__device__ float g_xr [MR*1024];            // x rounded to tf32
__device__ float g_wr [3*1024*1024];        // qkv_w rounded
__device__ float g_pwr[1024*1024];          // proj_w rounded
__device__ float g_qkv[(size_t)MR*3072];    // q(*0.125)|k|v rounded, row-major [s][3072]
__device__ float g_ctx[(size_t)MR*1024];    // attention out rounded

// ---------------- helpers ----------------
__device__ __forceinline__ uint32_t sm_u32(const void* p){
    uint32_t a;
    asm("{ .reg .u64 t; cvta.to.shared.u64 t, %1; cvt.u32.u64 %0, t; }" : "=r"(a) : "l"(p));
    return a;
}
__device__ __forceinline__ float rnaf(float x){
    uint32_t u; asm("cvt.rna.tf32.f32 %0, %1;" : "=r"(u) : "f"(x)); return __uint_as_float(u);
}
#define CP16(dst,src) asm volatile("cp.async.cg.shared.global [%0], [%1], 16;" :: "r"(dst),"l"(src))
#define CPC()  asm volatile("cp.async.commit_group;")
#define CPW(n) asm volatile("cp.async.wait_group %0;" :: "n"(n))

__device__ __forceinline__ void mma8(float* c, const uint32_t* a, const uint32_t* b){
    asm volatile("mma.sync.aligned.m16n8k8.row.col.f32.tf32.tf32.f32 "
        "{%0,%1,%2,%3}, {%4,%5,%6,%7}, {%8,%9}, {%0,%1,%2,%3};"
        : "+f"(c[0]),"+f"(c[1]),"+f"(c[2]),"+f"(c[3])
        : "r"(a[0]),"r"(a[1]),"r"(a[2]),"r"(a[3]), "r"(b[0]),"r"(b[1]));
}
__device__ __forceinline__ void ldsm4(uint32_t* r, uint32_t a){
    asm volatile("ldmatrix.sync.aligned.m8n8.x4.shared.b16 {%0,%1,%2,%3}, [%4];"
        : "=r"(r[0]),"=r"(r[1]),"=r"(r[2]),"=r"(r[3]) : "r"(a));
}

// ---------------------------------------------------------------------------
// fp32 -> tf32 (rna) pre-round. which: 0->g_xr, 1->g_wr, 2->g_pwr
// ---------------------------------------------------------------------------
__global__ void round_k(const float4* __restrict__ in, int which, int n4)
{
    int i = blockIdx.x * blockDim.x + threadIdx.x;
    if (i >= n4) return;
    float4* out = (which==0) ? (float4*)g_xr : (which==1) ? (float4*)g_wr : (float4*)g_pwr;
    float4 v = in[i];
    v.x = rnaf(v.x); v.y = rnaf(v.y); v.z = rnaf(v.z); v.w = rnaf(v.w);
    out[i] = v;
}

// ---------------------------------------------------------------------------
// tf32 mma.sync GEMM: C[M,N] = A[M,1024] @ B[N,1024]^T + bias
// CTA 128x256, warp tile 64x64 (2x4 warps), BK=16, 3-stage cp.async, ldmatrix.
// MODE 1: A=g_xr, B=g_wr, N=3072 -> g_qkv (rounded; q cols scaled 0.125)
// MODE 2: A=g_ctx, B=g_pwr, N=1024 -> C (plain fp32)
// dyn smem: A 3*8192 | B 3*16384 = 73728 B
// ---------------------------------------------------------------------------
template<int MODE>
__global__ __launch_bounds__(256, 1)
void mm_mma(const float* __restrict__ bias, float* __restrict__ C)
{
    extern __shared__ char smem[];
    const int N = (MODE==1) ? 3072 : 1024;
    uint32_t ab = sm_u32(smem);
    uint32_t bb = ab + 24576;
    const float* Ap = (MODE==1) ? g_xr : g_ctx;
    const float* Bp = (MODE==1) ? g_wr : g_pwr;
    float* Cp = (MODE==1) ? g_qkv : C;

    int tid = threadIdx.x, wid = tid>>5, lane = tid&31;
    int g = lane>>2, tg = lane&3;
    int wm = wid&1, wn = wid>>1;
    int bm = blockIdx.y*128, bn = blockIdx.x*256;

    auto aaddr = [&](int st,int r,int c){ return ab + st*8192  + r*64 + ((c ^ ((r>>1)&3))<<4); };
    auto baddr = [&](int st,int r,int c){ return bb + st*16384 + r*64 + ((c ^ ((r>>1)&3))<<4); };

    auto pf = [&](int kt, int st){
#pragma unroll
        for (int j=0;j<2;j++){
            int ci = j*256 + tid, r = ci>>2, c = ci&3;
            CP16(aaddr(st,r,c), Ap + (size_t)(bm+r)*1024 + kt*16 + c*4);
        }
#pragma unroll
        for (int j=0;j<4;j++){
            int ci = j*256 + tid, r = ci>>2, c = ci&3;
            CP16(baddr(st,r,c), Bp + (size_t)(bn+r)*1024 + kt*16 + c*4);
        }
    };

    float acc[4][8][4];
#pragma unroll
    for (int mt=0;mt<4;mt++)
#pragma unroll
        for (int nt=0;nt<8;nt++)
#pragma unroll
            for (int q=0;q<4;q++) acc[mt][nt][q] = 0.f;

    pf(0,0); CPC();
    pf(1,1); CPC();
    for (int kt=0; kt<64; kt++){
        int st = kt % 3;
        CPW(1);
        __syncthreads();
        if (kt+2 < 64) pf(kt+2, (kt+2)%3);
        CPC();
#pragma unroll
        for (int k8=0;k8<2;k8++){
            uint32_t a[4][4], b2[8][2];
#pragma unroll
            for (int mt=0;mt<4;mt++){
                int r = wm*64 + mt*16 + (lane&15);
                int c = k8*2 + ((lane>>4)&1);
                ldsm4(a[mt], aaddr(st,r,c));
            }
#pragma unroll
            for (int np=0;np<4;np++){
                int r = wn*64 + np*16 + (lane&7) + ((lane>>4)&1)*8;
                int c = k8*2 + ((lane>>3)&1);
                uint32_t t4[4];
                ldsm4(t4, baddr(st,r,c));
                b2[2*np][0]=t4[0];   b2[2*np][1]=t4[1];
                b2[2*np+1][0]=t4[2]; b2[2*np+1][1]=t4[3];
            }
#pragma unroll
            for (int mt=0;mt<4;mt++)
#pragma unroll
                for (int nt=0;nt<8;nt++)
                    mma8(acc[mt][nt], a[mt], b2[nt]);
        }
    }

#pragma unroll
    for (int mt=0;mt<4;mt++){
        int r0 = bm + wm*64 + mt*16 + g;
#pragma unroll
        for (int nt=0;nt<8;nt++){
            int c0 = bn + wn*64 + nt*8 + 2*tg;
            float b0 = bias[c0], b1 = bias[c0+1];
            float v0 = acc[mt][nt][0]+b0, v1 = acc[mt][nt][1]+b1;
            float v2 = acc[mt][nt][2]+b0, v3 = acc[mt][nt][3]+b1;
            if (MODE==1){
                float sc = (c0 < 1024) ? 0.125f : 1.f;
                v0=rnaf(v0*sc); v1=rnaf(v1*sc); v2=rnaf(v2*sc); v3=rnaf(v3*sc);
            }
            *(float2*)&Cp[(size_t)r0*N + c0]     = make_float2(v0,v1);
            *(float2*)&Cp[(size_t)(r0+8)*N + c0] = make_float2(v2,v3);
        }
    }
}

// ---------------------------------------------------------------------------
// Flash attention, mma.sync tf32. CTA = 256 queries of one (b,h), 256 thr,
// 8 warps x 32 rows. Bc=64 keys/iter, 32 iters. ldmatrix for Q/K/P fragments.
// dyn smem (bytes): Q[256x64f swz] 65536 | K 2x16384 | V 2x(64 rows x 272B) |
//                   P[256x64f swz] 65536  -> total 198656
// NOTE: u32 shared addresses are used ONLY inside asm (cp.async/ldmatrix);
//       all direct derefs go through the generic `smem` pointer.
// ---------------------------------------------------------------------------
__global__ __launch_bounds__(256, 1)
void attn_mma()
{
    extern __shared__ char smem[];
    uint32_t sb = sm_u32(smem);
    const uint32_t QO = 0, KO = 65536, VO = 98304, PO = 133120;

    int tid = threadIdx.x, wid = tid>>5, lane = tid&31;
    int g = lane>>2, tg = lane&3;
    int bh = blockIdx.y, b = bh>>4, hh = bh&15;
    int q0 = blockIdx.x * 256;

    const float* Qg  = g_qkv + (size_t)(b*2048 + q0)*3072 + hh*64;
    const float* KVg = g_qkv + (size_t)(b*2048)*3072 + 1024 + hh*64;

    auto qaddr = [&](int r,int c){ return sb + QO + r*256 + ((c ^ (r&7))<<4); };
    auto kaddr = [&](int st,int r,int c){ return sb + KO + st*16384 + r*256 + ((c ^ (r&7))<<4); };
    auto vaddr = [&](int st,int r,int c){ return sb + VO + st*17408 + r*272 + c*16; };
    auto paddr = [&](int r,int c){ return sb + PO + r*256 + ((c ^ (r&7))<<4); };

    // Q tile: 256 rows x 16 chunks
#pragma unroll
    for (int j=0;j<16;j++){
        int ci = j*256 + tid, r = ci>>4, c = ci&15;
        CP16(qaddr(r,c), Qg + (size_t)r*3072 + c*4);
    }
    auto pf = [&](int it, int st){
        int kt = it * 64;
#pragma unroll
        for (int j=0;j<4;j++){
            int ci = j*256 + tid, r = ci>>4, c = ci&15;
            CP16(kaddr(st,r,c), KVg + (size_t)(kt+r)*3072 + c*4);
        }
#pragma unroll
        for (int j=0;j<4;j++){
            int ci = j*256 + tid, r = ci>>4, c = ci&15;
            CP16(vaddr(st,r,c), KVg + (size_t)(kt+r)*3072 + 1024 + c*4);
        }
    };

    float o[2][8][4], m[2][2], l[2][2];
#pragma unroll
    for (int mt=0;mt<2;mt++){
        m[mt][0]=m[mt][1]=-1e30f; l[mt][0]=l[mt][1]=0.f;
#pragma unroll
        for (int nt=0;nt<8;nt++)
#pragma unroll
            for (int q=0;q<4;q++) o[mt][nt][q]=0.f;
    }

    pf(0,0); CPC();
    for (int it=0; it<32; it++){
        int st = it & 1;
        if (it+1 < 32){ pf(it+1, st^1); CPC(); CPW(1); } else CPW(0);
        __syncthreads();

        // ---- S = Q @ K^T : warp rows wid*32..+31, cols 0..63 ----
        float s[2][8][4];
#pragma unroll
        for (int mt=0;mt<2;mt++)
#pragma unroll
            for (int nt=0;nt<8;nt++)
#pragma unroll
                for (int q=0;q<4;q++) s[mt][nt][q]=0.f;
#pragma unroll
        for (int k8=0;k8<8;k8++){
            uint32_t a[2][4], b2[8][2];
#pragma unroll
            for (int mt=0;mt<2;mt++){
                int r = wid*32 + mt*16 + (lane&15);
                int c = k8*2 + ((lane>>4)&1);
                ldsm4(a[mt], qaddr(r,c));
            }
#pragma unroll
            for (int np=0;np<4;np++){
                int r = np*16 + (lane&7) + ((lane>>4)&1)*8;
                int c = k8*2 + ((lane>>3)&1);
                uint32_t t4[4];
                ldsm4(t4, kaddr(st,r,c));
                b2[2*np][0]=t4[0];   b2[2*np][1]=t4[1];
                b2[2*np+1][0]=t4[2]; b2[2*np+1][1]=t4[3];
            }
#pragma unroll
            for (int mt=0;mt<2;mt++)
#pragma unroll
                for (int nt=0;nt<8;nt++)
                    mma8(s[mt][nt], a[mt], b2[nt]);
        }

        // ---- online softmax: 4 row-states per thread (mt x half) ----
        float al[2][2];
#pragma unroll
        for (int mt=0;mt<2;mt++)
#pragma unroll
            for (int hf=0;hf<2;hf++){
                float mx = -1e30f;
#pragma unroll
                for (int nt=0;nt<8;nt++)
                    mx = fmaxf(mx, fmaxf(s[mt][nt][2*hf], s[mt][nt][2*hf+1]));
                mx = fmaxf(mx, __shfl_xor_sync(0xffffffffu, mx, 1));
                mx = fmaxf(mx, __shfl_xor_sync(0xffffffffu, mx, 2));
                float mn = fmaxf(m[mt][hf], mx);
                al[mt][hf] = __expf(m[mt][hf] - mn);
                m[mt][hf] = mn;
                float sum = 0.f;
#pragma unroll
                for (int nt=0;nt<8;nt++){
                    s[mt][nt][2*hf]   = __expf(s[mt][nt][2*hf]   - mn); sum += s[mt][nt][2*hf];
                    s[mt][nt][2*hf+1] = __expf(s[mt][nt][2*hf+1] - mn); sum += s[mt][nt][2*hf+1];
                }
                sum += __shfl_xor_sync(0xffffffffu, sum, 1);
                sum += __shfl_xor_sync(0xffffffffu, sum, 2);
                l[mt][hf] = l[mt][hf]*al[mt][hf] + sum;
            }
#pragma unroll
        for (int mt=0;mt<2;mt++)
#pragma unroll
            for (int nt=0;nt<8;nt++){
                o[mt][nt][0]*=al[mt][0]; o[mt][nt][1]*=al[mt][0];
                o[mt][nt][2]*=al[mt][1]; o[mt][nt][3]*=al[mt][1];
            }

        // ---- stage P (rounded) via GENERIC pointers, own-warp rows ----
#pragma unroll
        for (int mt=0;mt<2;mt++){
            int row = wid*32 + mt*16 + g;
            int coff = (2*tg & 3) * 4;
#pragma unroll
            for (int nt=0;nt<8;nt++){
                int ch = (nt*8 + 2*tg) >> 2;
                char* p0 = smem + PO + row*256     + (((ch ^ (row&7))<<4))     + coff;
                char* p1 = smem + PO + (row+8)*256 + (((ch ^ ((row+8)&7))<<4)) + coff;
                *(float2*)p0 = make_float2(rnaf(s[mt][nt][0]), rnaf(s[mt][nt][1]));
                *(float2*)p1 = make_float2(rnaf(s[mt][nt][2]), rnaf(s[mt][nt][3]));
            }
        }
        __syncwarp();

        // ---- O += P @ V ----
#pragma unroll
        for (int k8=0;k8<8;k8++){
            uint32_t a[2][4];
#pragma unroll
            for (int mt=0;mt<2;mt++){
                int r = wid*32 + mt*16 + (lane&15);
                int c = k8*2 + ((lane>>4)&1);
                ldsm4(a[mt], paddr(r,c));
            }
            const float* v0 = (const float*)(smem + VO + st*17408 + (k8*8+tg  )*272);
            const float* v1 = (const float*)(smem + VO + st*17408 + (k8*8+tg+4)*272);
#pragma unroll
            for (int nt=0;nt<8;nt++){
                uint32_t b2[2] = { __float_as_uint(v0[nt*8+g]), __float_as_uint(v1[nt*8+g]) };
                mma8(o[0][nt], a[0], b2);
                mma8(o[1][nt], a[1], b2);
            }
        }
        __syncthreads();
    }

    // ---- epilogue: normalize, round, write ctx ----
#pragma unroll
    for (int mt=0;mt<2;mt++){
        float i0 = 1.f/l[mt][0], i1 = 1.f/l[mt][1];
        int r0 = q0 + wid*32 + mt*16 + g;
        float* Cg = g_ctx + (size_t)(b*2048 + r0)*1024 + hh*64;
#pragma unroll
        for (int nt=0;nt<8;nt++){
            int c = nt*8 + 2*tg;
            *(float2*)&Cg[c]          = make_float2(rnaf(o[mt][nt][0]*i0), rnaf(o[mt][nt][1]*i0));
            *(float2*)&Cg[8*1024 + c] = make_float2(rnaf(o[mt][nt][2]*i1), rnaf(o[mt][nt][3]*i1));
        }
    }
}

// ---------------------------------------------------------------------------
extern "C" void kernel_launch(void* const* d_in, const int* in_sizes, int n_in,
                              void* d_out, int out_size)
{
    const float* x      = (const float*)d_in[0];
    const float* qkv_w  = (const float*)d_in[1];
    const float* qkv_b  = (const float*)d_in[2];
    const float* proj_w = (const float*)d_in[3];
    const float* proj_b = (const float*)d_in[4];
    float* out = (float*)d_out;
    (void)in_sizes; (void)n_in; (void)out_size;

    const int GSM = 73728;    // GEMM: 3-stage A(8K)+B(16K)
    const int ASM = 198656;   // attention
    cudaFuncSetAttribute(mm_mma<1>, cudaFuncAttributeMaxDynamicSharedMemorySize, GSM);
    cudaFuncSetAttribute(mm_mma<2>, cudaFuncAttributeMaxDynamicSharedMemorySize, GSM);
    cudaFuncSetAttribute(attn_mma,  cudaFuncAttributeMaxDynamicSharedMemorySize, ASM);

    round_k<<<4096, 256>>>((const float4*)x,      0, 1048576);
    round_k<<<3072, 256>>>((const float4*)qkv_w,  1,  786432);
    round_k<<<1024, 256>>>((const float4*)proj_w, 2,  262144);

    mm_mma<1><<<dim3(12, 32), 256, GSM>>>(qkv_b, nullptr);
    attn_mma  <<<dim3( 8, 32), 256, ASM>>>();
    mm_mma<2><<<dim3( 4, 32), 256, GSM>>>(proj_b, out);
}